// round 3
// baseline (speedup 1.0000x reference)
#include <cuda_runtime.h>
#include <math.h>

#define NTOK 4096
#define DIM  1024
#define HID  2048
#define NEXP 8
#define KSEL 2

// ---------------- scratch (static device globals; no allocation) ----------------
__device__ int   g_counts[NEXP];
__device__ int   g_offsets[NEXP + 1];
__device__ int   g_tokens[NEXP * NTOK];          // token id per (expert, pos)
__device__ int   g_slot[NTOK * KSEL];            // per token: global pair slot of its k-th expert
__device__ float g_gateval[NTOK * KSEL];         // per token: gate value of its k-th selection
__device__ float g_h[(size_t)NTOK * KSEL * HID]; // 8192 x 2048 fp32 = 64 MB
__device__ float g_o[(size_t)NTOK * KSEL * DIM]; // 8192 x 1024 fp32 = 32 MB (pre-gate FFN2 out)

// ---------------- kernel: zero routing counters ----------------
__global__ void zero_counts_kernel() {
    if (threadIdx.x < NEXP) g_counts[threadIdx.x] = 0;
}

// ---------------- kernel: gating (one warp per token) ----------------
__global__ void gating_kernel(const float* __restrict__ x,
                              const float* __restrict__ Wg,
                              const int* __restrict__ task_ptr) {
    int gw   = (blockIdx.x * blockDim.x + threadIdx.x) >> 5;
    int lane = threadIdx.x & 31;
    if (gw >= NTOK) return;

    const int task = task_ptr[0];
    const float* xr = x + (size_t)gw * DIM;
    const float* wg = Wg + (size_t)task * (DIM * NEXP);

    float s0 = 0.f, s1 = 0.f, s2 = 0.f, s3 = 0.f, s4 = 0.f, s5 = 0.f, s6 = 0.f, s7 = 0.f;
    for (int d = lane; d < DIM; d += 32) {
        float xv = xr[d];
        const float4* w4 = reinterpret_cast<const float4*>(wg + (size_t)d * NEXP);
        float4 a = w4[0];
        float4 b = w4[1];
        s0 += xv * a.x; s1 += xv * a.y; s2 += xv * a.z; s3 += xv * a.w;
        s4 += xv * b.x; s5 += xv * b.y; s6 += xv * b.z; s7 += xv * b.w;
    }
    #pragma unroll
    for (int off = 16; off > 0; off >>= 1) {
        s0 += __shfl_down_sync(0xffffffffu, s0, off);
        s1 += __shfl_down_sync(0xffffffffu, s1, off);
        s2 += __shfl_down_sync(0xffffffffu, s2, off);
        s3 += __shfl_down_sync(0xffffffffu, s3, off);
        s4 += __shfl_down_sync(0xffffffffu, s4, off);
        s5 += __shfl_down_sync(0xffffffffu, s5, off);
        s6 += __shfl_down_sync(0xffffffffu, s6, off);
        s7 += __shfl_down_sync(0xffffffffu, s7, off);
    }
    if (lane == 0) {
        float l[NEXP] = {s0, s1, s2, s3, s4, s5, s6, s7};
        float mx = l[0];
        #pragma unroll
        for (int e = 1; e < NEXP; e++) mx = fmaxf(mx, l[e]);
        float p[NEXP];
        float sum = 0.f;
        #pragma unroll
        for (int e = 0; e < NEXP; e++) { p[e] = expf(l[e] - mx); sum += p[e]; }
        float inv = 1.0f / sum;

        // top-1: strict > from low index == jax top_k tie behavior
        int i1 = 0;
        #pragma unroll
        for (int e = 1; e < NEXP; e++) if (l[e] > l[i1]) i1 = e;
        // top-2: strict > from low index, skipping i1
        int i2 = (i1 == 0) ? 1 : 0;
        #pragma unroll
        for (int e = 0; e < NEXP; e++) if (e != i1 && l[e] > l[i2]) i2 = e;

        float g1 = p[i1] * inv;
        float g2 = p[i2] * inv;

        int pos1 = atomicAdd(&g_counts[i1], 1);
        g_tokens[i1 * NTOK + pos1] = gw;
        int pos2 = atomicAdd(&g_counts[i2], 1);
        g_tokens[i2 * NTOK + pos2] = gw;

        // per-token records (deterministic combine order: top-1 then top-2)
        g_gateval[gw * KSEL + 0] = g1;
        g_gateval[gw * KSEL + 1] = g2;
        g_slot   [gw * KSEL + 0] = i1 * NTOK + pos1;   // provisional: expert-local; fixed in scan
        g_slot   [gw * KSEL + 1] = i2 * NTOK + pos2;
    }
}

// ---------------- kernel: scan counts, rebase slots to compacted offsets ----------------
__global__ void scan_kernel() {
    __shared__ int offs[NEXP];
    if (threadIdx.x == 0) {
        int o = 0;
        #pragma unroll
        for (int e = 0; e < NEXP; e++) { g_offsets[e] = o; offs[e] = o; o += g_counts[e]; }
        g_offsets[NEXP] = o;
    }
    __syncthreads();
    // rebase g_slot entries: slot = offsets[e] + pos
    for (int i = threadIdx.x; i < NTOK * KSEL; i += blockDim.x) {
        int s = g_slot[i];
        int e = s / NTOK;
        int pos = s - e * NTOK;
        g_slot[i] = offs[e] + pos;
    }
}

// ---------------- grouped SGEMM tiles ----------------
#define BM 128
#define BN 128
#define BK 8
#define TM 8
#define TN 8

// ffn1: h[pairSlot, 0:H] = gelu( x[token] @ W1[e] + b1[e] )
__global__ __launch_bounds__(256)
void ffn1_kernel(const float* __restrict__ x,
                 const float* __restrict__ W1,
                 const float* __restrict__ b1) {
    const int e      = blockIdx.z;
    const int count  = g_counts[e];
    const int mStart = blockIdx.x * BM;
    if (mStart >= count) return;
    const int nStart = blockIdx.y * BN;
    const int hBase  = g_offsets[e];
    const float* Bw  = W1 + (size_t)e * DIM * HID;   // [D, H] row-major

    __shared__ float As[BK][BM];
    __shared__ float Bs[BK][BN];

    const int tid = threadIdx.x;
    const int tx = tid & 15;        // 16 cols of threads
    const int ty = tid >> 4;        // 16 rows of threads

    // A load: one float4 per thread (128 rows x 8 k)
    const int aRow = tid >> 1;
    const int aCol = (tid & 1) * 4;
    const bool aValid = (mStart + aRow) < count;
    const float* aPtr = aValid ? (x + (size_t)g_tokens[e * NTOK + mStart + aRow] * DIM) : x;

    // B load: one float4 per thread (8 k x 128 n)
    const int bRow = tid >> 5;
    const int bCol = (tid & 31) * 4;
    const float* bPtr = Bw + (size_t)bRow * HID + nStart + bCol;

    float acc[TM][TN];
    #pragma unroll
    for (int i = 0; i < TM; i++)
        #pragma unroll
        for (int j = 0; j < TN; j++) acc[i][j] = 0.f;

    for (int k0 = 0; k0 < DIM; k0 += BK) {
        float4 av = make_float4(0.f, 0.f, 0.f, 0.f);
        if (aValid) av = *reinterpret_cast<const float4*>(aPtr + k0 + aCol);
        float4 bv = *reinterpret_cast<const float4*>(bPtr + (size_t)k0 * HID);

        As[aCol + 0][aRow] = av.x;
        As[aCol + 1][aRow] = av.y;
        As[aCol + 2][aRow] = av.z;
        As[aCol + 3][aRow] = av.w;
        *reinterpret_cast<float4*>(&Bs[bRow][bCol]) = bv;
        __syncthreads();

        #pragma unroll
        for (int k = 0; k < BK; k++) {
            float ra[TM], rb[TN];
            #pragma unroll
            for (int i = 0; i < TM; i++) ra[i] = As[k][ty * TM + i];
            #pragma unroll
            for (int j = 0; j < TN; j++) rb[j] = Bs[k][tx * TN + j];
            #pragma unroll
            for (int i = 0; i < TM; i++)
                #pragma unroll
                for (int j = 0; j < TN; j++) acc[i][j] += ra[i] * rb[j];
        }
        __syncthreads();
    }

    #pragma unroll
    for (int i = 0; i < TM; i++) {
        int gm = mStart + ty * TM + i;
        if (gm >= count) continue;
        float* hRow = g_h + (size_t)(hBase + gm) * HID + nStart;
        #pragma unroll
        for (int j = 0; j < TN; j++) {
            int col = tx * TN + j;
            float v = acc[i][j] + b1[e * HID + nStart + col];
            v = 0.5f * v * (1.0f + erff(v * 0.70710678118654752f));  // exact gelu
            hRow[col] = v;
        }
    }
}

// ffn2: o[pairSlot, 0:D] = h[pairSlot] @ W2[e] + b2[e]   (pre-gate, no atomics)
__global__ __launch_bounds__(256)
void ffn2_kernel(const float* __restrict__ W2,
                 const float* __restrict__ b2) {
    const int e      = blockIdx.z;
    const int count  = g_counts[e];
    const int mStart = blockIdx.x * BM;
    if (mStart >= count) return;
    const int nStart = blockIdx.y * BN;
    const int hBase  = g_offsets[e];
    const float* Bw  = W2 + (size_t)e * HID * DIM;   // [H, D] row-major

    __shared__ float As[BK][BM];
    __shared__ float Bs[BK][BN];

    const int tid = threadIdx.x;
    const int tx = tid & 15;
    const int ty = tid >> 4;

    const int aRow = tid >> 1;
    const int aCol = (tid & 1) * 4;
    const bool aValid = (mStart + aRow) < count;
    const float* aPtr = g_h + (size_t)(hBase + (aValid ? (mStart + aRow) : 0)) * HID;

    const int bRow = tid >> 5;
    const int bCol = (tid & 31) * 4;
    const float* bPtr = Bw + (size_t)bRow * DIM + nStart + bCol;

    float acc[TM][TN];
    #pragma unroll
    for (int i = 0; i < TM; i++)
        #pragma unroll
        for (int j = 0; j < TN; j++) acc[i][j] = 0.f;

    for (int k0 = 0; k0 < HID; k0 += BK) {
        float4 av = make_float4(0.f, 0.f, 0.f, 0.f);
        if (aValid) av = *reinterpret_cast<const float4*>(aPtr + k0 + aCol);
        float4 bv = *reinterpret_cast<const float4*>(bPtr + (size_t)k0 * DIM);

        As[aCol + 0][aRow] = av.x;
        As[aCol + 1][aRow] = av.y;
        As[aCol + 2][aRow] = av.z;
        As[aCol + 3][aRow] = av.w;
        *reinterpret_cast<float4*>(&Bs[bRow][bCol]) = bv;
        __syncthreads();

        #pragma unroll
        for (int k = 0; k < BK; k++) {
            float ra[TM], rb[TN];
            #pragma unroll
            for (int i = 0; i < TM; i++) ra[i] = As[k][ty * TM + i];
            #pragma unroll
            for (int j = 0; j < TN; j++) rb[j] = Bs[k][tx * TN + j];
            #pragma unroll
            for (int i = 0; i < TM; i++)
                #pragma unroll
                for (int j = 0; j < TN; j++) acc[i][j] += ra[i] * rb[j];
        }
        __syncthreads();
    }

    #pragma unroll
    for (int i = 0; i < TM; i++) {
        int gm = mStart + ty * TM + i;
        if (gm >= count) continue;
        float* oRow = g_o + (size_t)(hBase + gm) * DIM + nStart;
        #pragma unroll
        for (int j = 0; j < TN; j++) {
            int col = tx * TN + j;
            oRow[col] = acc[i][j] + b2[e * DIM + nStart + col];
        }
    }
}

// combine: y[tok] = g1 * o[slot1] + g2 * o[slot2]  (fixed order -> deterministic)
__global__ __launch_bounds__(256)
void combine_kernel(float* __restrict__ y) {
    int idx = blockIdx.x * blockDim.x + threadIdx.x;           // over NTOK * DIM/4
    int tok = idx / (DIM / 4);
    int c4  = idx - tok * (DIM / 4);
    if (tok >= NTOK) return;

    int   s1 = g_slot[tok * KSEL + 0];
    int   s2 = g_slot[tok * KSEL + 1];
    float g1 = g_gateval[tok * KSEL + 0];
    float g2 = g_gateval[tok * KSEL + 1];

    const float4* o1 = reinterpret_cast<const float4*>(g_o + (size_t)s1 * DIM) + c4;
    const float4* o2 = reinterpret_cast<const float4*>(g_o + (size_t)s2 * DIM) + c4;
    float4 a = *o1;
    float4 b = *o2;
    float4 r;
    r.x = g1 * a.x + g2 * b.x;
    r.y = g1 * a.y + g2 * b.y;
    r.z = g1 * a.z + g2 * b.z;
    r.w = g1 * a.w + g2 * b.w;
    reinterpret_cast<float4*>(y + (size_t)tok * DIM)[c4] = r;
}

// ---------------- launch ----------------
extern "C" void kernel_launch(void* const* d_in, const int* in_sizes, int n_in,
                              void* d_out, int out_size) {
    const float* x    = (const float*)d_in[0];
    const float* Wg   = (const float*)d_in[1];
    const float* W1   = (const float*)d_in[2];
    const float* b1   = (const float*)d_in[3];
    const float* W2   = (const float*)d_in[4];
    const float* b2   = (const float*)d_in[5];
    const int*   task = (const int*)  d_in[6];
    float* y = (float*)d_out;

    zero_counts_kernel<<<1, 32>>>();
    gating_kernel<<<(NTOK * 32 + 255) / 256, 256>>>(x, Wg, task);
    scan_kernel<<<1, 256>>>();

    dim3 g1(NTOK / BM, HID / BN, NEXP);   // 32 x 16 x 8 (idle tiles early-exit)
    ffn1_kernel<<<g1, 256>>>(x, W1, b1);

    dim3 g2(NTOK / BM, DIM / BN, NEXP);   // 32 x 8 x 8
    ffn2_kernel<<<g2, 256>>>(W2, b2);

    combine_kernel<<<(NTOK * (DIM / 4) + 255) / 256, 256>>>(y);
}

// round 7
// speedup vs baseline: 2.1382x; 2.1382x over previous
#include <cuda_runtime.h>
#include <cuda_bf16.h>
#include <math.h>
#include <stdint.h>

#define NTOK 4096
#define DIM  1024
#define HID  2048
#define NEXP 8
#define KSEL 2
#define NPAIR (NTOK * KSEL)

// ============ static scratch: ~64 MB total (96 MB was proven OK in R3) ============
__device__ int   g_counts[NEXP];
__device__ int   g_offsets[NEXP + 1];
__device__ int   g_tokens[NEXP * NTOK];            // token id per (expert, pos)
__device__ float g_slotgate[NEXP * NTOK];          // gate value per (expert, pos)
__device__ unsigned short g_hhi[(size_t)NPAIR * HID];  // 32 MB
__device__ unsigned short g_hlo[(size_t)NPAIR * HID];  // 32 MB

// ============ PTX helpers (sm_80-level PTX; target is plain sm_100) ============
__device__ __forceinline__ uint32_t smem_u32(const void* p) {
    uint32_t a;
    asm("{ .reg .u64 t; cvta.to.shared.u64 t, %1; cvt.u32.u64 %0, t; }" : "=r"(a) : "l"(p));
    return a;
}
__device__ __forceinline__ void ldsm4(uint32_t* r, uint32_t addr) {
    asm volatile("ldmatrix.sync.aligned.m8n8.x4.shared.b16 {%0,%1,%2,%3}, [%4];"
                 : "=r"(r[0]), "=r"(r[1]), "=r"(r[2]), "=r"(r[3]) : "r"(addr));
}
__device__ __forceinline__ void ldsm4t(uint32_t* r, uint32_t addr) {
    asm volatile("ldmatrix.sync.aligned.m8n8.x4.trans.shared.b16 {%0,%1,%2,%3}, [%4];"
                 : "=r"(r[0]), "=r"(r[1]), "=r"(r[2]), "=r"(r[3]) : "r"(addr));
}
__device__ __forceinline__ void mma16816(float* d, const uint32_t* a, const uint32_t* b) {
    asm volatile(
        "mma.sync.aligned.m16n8k16.row.col.f32.bf16.bf16.f32 "
        "{%0,%1,%2,%3}, {%4,%5,%6,%7}, {%8,%9}, {%0,%1,%2,%3};"
        : "+f"(d[0]), "+f"(d[1]), "+f"(d[2]), "+f"(d[3])
        : "r"(a[0]), "r"(a[1]), "r"(a[2]), "r"(a[3]), "r"(b[0]), "r"(b[1]));
}
__device__ __forceinline__ void split2(float v, unsigned short& hi, unsigned short& lo) {
    __nv_bfloat16 h = __float2bfloat16(v);
    hi = __bfloat16_as_ushort(h);
    lo = __bfloat16_as_ushort(__float2bfloat16(v - __bfloat162float(h)));
}
// split float4 -> packed hi (2x u32) and lo (2x u32)
__device__ __forceinline__ void split4(float4 v, uint2& ph, uint2& pl) {
    unsigned short h0, l0, h1, l1, h2, l2, h3, l3;
    split2(v.x, h0, l0); split2(v.y, h1, l1); split2(v.z, h2, l2); split2(v.w, h3, l3);
    ph = make_uint2((uint32_t)h0 | ((uint32_t)h1 << 16), (uint32_t)h2 | ((uint32_t)h3 << 16));
    pl = make_uint2((uint32_t)l0 | ((uint32_t)l1 << 16), (uint32_t)l2 | ((uint32_t)l3 << 16));
}

// ============ routing ============
__global__ void zero_counts_kernel() {
    if (threadIdx.x < NEXP) g_counts[threadIdx.x] = 0;
}

__global__ void gating_kernel(const float* __restrict__ x,
                              const float* __restrict__ Wg,
                              const int* __restrict__ task_ptr) {
    int gw   = (blockIdx.x * blockDim.x + threadIdx.x) >> 5;
    int lane = threadIdx.x & 31;
    if (gw >= NTOK) return;

    const int task = task_ptr[0];
    const float* xr = x + (size_t)gw * DIM;
    const float* wg = Wg + (size_t)task * (DIM * NEXP);

    float s0 = 0.f, s1 = 0.f, s2 = 0.f, s3 = 0.f, s4 = 0.f, s5 = 0.f, s6 = 0.f, s7 = 0.f;
    for (int d = lane; d < DIM; d += 32) {
        float xv = xr[d];
        const float4* w4 = reinterpret_cast<const float4*>(wg + (size_t)d * NEXP);
        float4 a = w4[0];
        float4 b = w4[1];
        s0 += xv * a.x; s1 += xv * a.y; s2 += xv * a.z; s3 += xv * a.w;
        s4 += xv * b.x; s5 += xv * b.y; s6 += xv * b.z; s7 += xv * b.w;
    }
    #pragma unroll
    for (int off = 16; off > 0; off >>= 1) {
        s0 += __shfl_down_sync(0xffffffffu, s0, off);
        s1 += __shfl_down_sync(0xffffffffu, s1, off);
        s2 += __shfl_down_sync(0xffffffffu, s2, off);
        s3 += __shfl_down_sync(0xffffffffu, s3, off);
        s4 += __shfl_down_sync(0xffffffffu, s4, off);
        s5 += __shfl_down_sync(0xffffffffu, s5, off);
        s6 += __shfl_down_sync(0xffffffffu, s6, off);
        s7 += __shfl_down_sync(0xffffffffu, s7, off);
    }
    if (lane == 0) {
        float l[NEXP] = {s0, s1, s2, s3, s4, s5, s6, s7};
        float mx = l[0];
        #pragma unroll
        for (int e = 1; e < NEXP; e++) mx = fmaxf(mx, l[e]);
        float p[NEXP];
        float sum = 0.f;
        #pragma unroll
        for (int e = 0; e < NEXP; e++) { p[e] = expf(l[e] - mx); sum += p[e]; }
        float inv = 1.0f / sum;

        int i1 = 0;
        #pragma unroll
        for (int e = 1; e < NEXP; e++) if (l[e] > l[i1]) i1 = e;
        int i2 = (i1 == 0) ? 1 : 0;
        #pragma unroll
        for (int e = 0; e < NEXP; e++) if (e != i1 && l[e] > l[i2]) i2 = e;

        int pos1 = atomicAdd(&g_counts[i1], 1);
        g_tokens  [i1 * NTOK + pos1] = gw;
        g_slotgate[i1 * NTOK + pos1] = p[i1] * inv;
        int pos2 = atomicAdd(&g_counts[i2], 1);
        g_tokens  [i2 * NTOK + pos2] = gw;
        g_slotgate[i2 * NTOK + pos2] = p[i2] * inv;
    }
}

__global__ void scan_kernel() {
    if (threadIdx.x == 0) {
        int o = 0;
        #pragma unroll
        for (int e = 0; e < NEXP; e++) { g_offsets[e] = o; o += g_counts[e]; }
        g_offsets[NEXP] = o;
    }
}

// ============ mma.sync grouped GEMM (bf16x3 split, on-the-fly conversion) ============
// 128x128 tile, BK=32, 256 threads = 8 warps (4 m x 2 n).
// A SMEM: [128][32] bf16, 80B pitch (64B + 16B pad)  -> non-trans ldmatrix
// B SMEM: [32][128] bf16, 272B pitch (256B + 16B pad) -> trans ldmatrix
#define BK     32
#define ROWA   80
#define ROWB   272
#define A_TILE (128 * ROWA)       // 10240
#define B_TILE (BK * ROWB)        // 8704

template<int KLEN, bool GELU>
__global__ __launch_bounds__(256, 1)
void moe_gemm_kernel(const float* __restrict__ x,
                     const float* __restrict__ W,
                     const float* __restrict__ bias,
                     float* __restrict__ y,
                     int NTOT) {
    const int e      = blockIdx.z;
    const int count  = g_counts[e];
    const int mStart = blockIdx.x * 128;
    if (mStart >= count) return;
    const int nStart = blockIdx.y * 128;
    const int hBase  = g_offsets[e];

    __shared__ char smem[2 * A_TILE + 2 * B_TILE];    // 37888 B, static
    const uint32_t sAhi = smem_u32(smem);
    const uint32_t sAlo = sAhi + A_TILE;
    const uint32_t sBhi = sAlo + A_TILE;
    const uint32_t sBlo = sBhi + B_TILE;

    const int tid  = threadIdx.x;
    const int wid  = tid >> 5;
    const int lane = tid & 31;
    const int wm   = wid & 3;        // 4 warps along M (32 rows)
    const int wn   = wid >> 2;       // 2 warps along N (64 cols)

    const float* Wb = W + (size_t)e * KLEN * NTOT;    // [KLEN][NTOT] row-major

    // per-thread A-source row indices (4 sub-loads)
    int a_r[4];
    const int* toks = g_tokens + e * NTOK;
    #pragma unroll
    for (int j = 0; j < 4; j++) {
        int id = tid + 256 * j;
        a_r[j] = GELU ? (id >> 3) : ((id & 511) >> 2);
    }

    float4 areg[4];   // ffn1: x fp32 chunks
    uint4  hreg[4];   // ffn2: pre-split h chunks (j<2: hi, j>=2: lo? see mapping)
    float4 breg[4];

    auto load_regs = [&](int k0) {
        if (GELU) {
            // A: 128 rows x 8 float4 (32 fp32) = 1024 chunks, 4/thread
            #pragma unroll
            for (int j = 0; j < 4; j++) {
                int id = tid + 256 * j;
                int r  = id >> 3;
                int c4 = id & 7;
                int gm = mStart + r;
                if (gm >= count) gm = count - 1;
                int tok = toks[gm];
                areg[j] = *reinterpret_cast<const float4*>(x + (size_t)tok * DIM + k0 + c4 * 4);
            }
        } else {
            // A: hi & lo arrays, 128 rows x 4 uint4 (32 bf16) each = 1024 chunks, 4/thread
            #pragma unroll
            for (int j = 0; j < 4; j++) {
                int id  = tid + 256 * j;
                int arr = id >> 9;           // 0: hi, 1: lo
                int cid = id & 511;
                int r   = cid >> 2;
                int c   = cid & 3;
                int gm  = mStart + r;
                if (gm >= count) gm = count - 1;
                const unsigned short* src = (arr ? g_hlo : g_hhi) + (size_t)(hBase + gm) * HID + k0 + c * 8;
                hreg[j] = *reinterpret_cast<const uint4*>(src);
            }
        }
        // B: 32 k-rows x 32 float4 (128 fp32) = 1024 chunks, 4/thread
        #pragma unroll
        for (int j = 0; j < 4; j++) {
            int id = tid + 256 * j;
            int kr = id >> 5;
            int c4 = id & 31;
            breg[j] = *reinterpret_cast<const float4*>(Wb + (size_t)(k0 + kr) * NTOT + nStart + c4 * 4);
        }
    };

    auto store_stage = [&]() {
        if (GELU) {
            #pragma unroll
            for (int j = 0; j < 4; j++) {
                int id = tid + 256 * j;
                int r  = id >> 3;
                int c4 = id & 7;
                uint2 ph, pl;
                split4(areg[j], ph, pl);
                *reinterpret_cast<uint2*>((char*)smem + (sAhi - sAhi) + r * ROWA + c4 * 8) = ph;      // Ahi
                *reinterpret_cast<uint2*>((char*)smem + A_TILE + r * ROWA + c4 * 8) = pl;              // Alo
            }
        } else {
            #pragma unroll
            for (int j = 0; j < 4; j++) {
                int id  = tid + 256 * j;
                int arr = id >> 9;
                int cid = id & 511;
                int r   = cid >> 2;
                int c   = cid & 3;
                *reinterpret_cast<uint4*>((char*)smem + arr * A_TILE + r * ROWA + c * 16) = hreg[j];
            }
        }
        #pragma unroll
        for (int j = 0; j < 4; j++) {
            int id = tid + 256 * j;
            int kr = id >> 5;
            int c4 = id & 31;
            uint2 ph, pl;
            split4(breg[j], ph, pl);
            *reinterpret_cast<uint2*>((char*)smem + 2 * A_TILE + kr * ROWB + c4 * 8) = ph;             // Bhi
            *reinterpret_cast<uint2*>((char*)smem + 2 * A_TILE + B_TILE + kr * ROWB + c4 * 8) = pl;    // Blo
        }
    };

    float acc[2][8][4];
    #pragma unroll
    for (int i = 0; i < 2; i++)
        #pragma unroll
        for (int j = 0; j < 8; j++)
            #pragma unroll
            for (int q = 0; q < 4; q++) acc[i][j][q] = 0.f;

    constexpr int NC = KLEN / BK;

    load_regs(0);
    store_stage();
    __syncthreads();

    for (int k = 0; k < NC; k++) {
        if (k + 1 < NC) load_regs((k + 1) * BK);   // LDG in flight during compute

        #pragma unroll
        for (int kk = 0; kk < 2; kk++) {
            const int kof = kk * 16;
            // A fragments (non-trans): rows = wm*32 + mt*16 + (lane&15), k-half by lane&16
            uint32_t ah[2][4], al[2][4];
            #pragma unroll
            for (int mt = 0; mt < 2; mt++) {
                uint32_t off = (uint32_t)((wm * 32 + mt * 16 + (lane & 15)) * ROWA
                                          + (kof + ((lane & 16) ? 8 : 0)) * 2);
                ldsm4(ah[mt], sAhi + off);
                ldsm4(al[mt], sAlo + off);
            }
            #pragma unroll
            for (int p = 0; p < 4; p++) {
                // B fragments (trans) for two n8 tiles at nb, nb+8
                int nb = wn * 64 + p * 16;
                int krow = kof + ((lane & 8) ? 8 : 0) + (lane & 7);
                int ncol = nb + ((lane & 16) ? 8 : 0);
                uint32_t boff = (uint32_t)(krow * ROWB + ncol * 2);
                uint32_t bh[4], bl[4];
                ldsm4t(bh, sBhi + boff);
                ldsm4t(bl, sBlo + boff);
                #pragma unroll
                for (int t = 0; t < 2; t++) {
                    uint32_t bhf[2] = {bh[2 * t], bh[2 * t + 1]};
                    uint32_t blf[2] = {bl[2 * t], bl[2 * t + 1]};
                    #pragma unroll
                    for (int mt = 0; mt < 2; mt++) {
                        float* d = acc[mt][2 * p + t];
                        mma16816(d, ah[mt], bhf);   // hi*hi
                        mma16816(d, ah[mt], blf);   // hi*lo
                        mma16816(d, al[mt], bhf);   // lo*hi
                    }
                }
            }
        }
        __syncthreads();
        if (k + 1 < NC) {
            store_stage();
            __syncthreads();
        }
    }

    // ---- epilogue: D fragment rows l/4 (+8), cols 2(l%4)+{0,1} ----
    const int r0 = lane >> 2;
    const int c0 = 2 * (lane & 3);
    const float* gates = g_slotgate + e * NTOK;
    #pragma unroll
    for (int mt = 0; mt < 2; mt++) {
        #pragma unroll
        for (int nt = 0; nt < 8; nt++) {
            const float* d = acc[mt][nt];
            int lrow = mStart + wm * 32 + mt * 16 + r0;
            int col  = nStart + wn * 64 + nt * 8 + c0;
            float bs0 = bias[(size_t)e * NTOT + col];
            float bs1 = bias[(size_t)e * NTOT + col + 1];
            #pragma unroll
            for (int h = 0; h < 2; h++) {
                int rr = lrow + h * 8;
                if (rr >= count) continue;
                float v0 = d[2 * h + 0] + bs0;
                float v1 = d[2 * h + 1] + bs1;
                if (GELU) {
                    v0 = 0.5f * v0 * (1.0f + erff(v0 * 0.70710678118654752f));
                    v1 = 0.5f * v1 * (1.0f + erff(v1 * 0.70710678118654752f));
                    unsigned short h0, l0, h1, l1;
                    split2(v0, h0, l0);
                    split2(v1, h1, l1);
                    size_t ob = (size_t)(hBase + rr) * HID + col;
                    *reinterpret_cast<uint32_t*>(g_hhi + ob) = (uint32_t)h0 | ((uint32_t)h1 << 16);
                    *reinterpret_cast<uint32_t*>(g_hlo + ob) = (uint32_t)l0 | ((uint32_t)l1 << 16);
                } else {
                    int   tok  = toks[rr];
                    float gate = gates[rr];
                    float* yr = y + (size_t)tok * DIM + col;
                    atomicAdd(&yr[0], gate * v0);
                    atomicAdd(&yr[1], gate * v1);
                }
            }
        }
    }
}

// ============ launch ============
extern "C" void kernel_launch(void* const* d_in, const int* in_sizes, int n_in,
                              void* d_out, int out_size) {
    const float* x    = (const float*)d_in[0];
    const float* Wg   = (const float*)d_in[1];
    const float* W1   = (const float*)d_in[2];
    const float* b1   = (const float*)d_in[3];
    const float* W2   = (const float*)d_in[4];
    const float* b2   = (const float*)d_in[5];
    const int*   task = (const int*)  d_in[6];
    float* y = (float*)d_out;

    cudaMemsetAsync(d_out, 0, (size_t)out_size * sizeof(float), 0);

    zero_counts_kernel<<<1, 32>>>();
    gating_kernel<<<(NTOK * 32 + 255) / 256, 256>>>(x, Wg, task);
    scan_kernel<<<1, 32>>>();

    // ffn1: h = gelu(x @ W1 + b1), stored as bf16 hi/lo
    moe_gemm_kernel<DIM, true><<<dim3(NTOK / 128, HID / 128, NEXP), 256>>>(x, W1, b1, y, HID);
    // ffn2: y += gate * (h @ W2 + b2)  (atomic combine)
    moe_gemm_kernel<HID, false><<<dim3(NTOK / 128, DIM / 128, NEXP), 256>>>(x, W2, b2, y, DIM);
}

// round 9
// speedup vs baseline: 2.1902x; 1.0243x over previous
#include <cuda_runtime.h>
#include <cuda_bf16.h>
#include <math.h>
#include <stdint.h>

#define NTOK 4096
#define DIM  1024
#define HID  2048
#define NEXP 8
#define KSEL 2
#define NPAIR (NTOK * KSEL)

// ============ static scratch: ~64 MB (96 MB proven OK in R3) ============
__device__ int   g_counts[NEXP];
__device__ int   g_offsets[NEXP + 1];
__device__ int   g_tokens[NEXP * NTOK];
__device__ float g_slotgate[NEXP * NTOK];
__device__ unsigned short g_hhi[(size_t)NPAIR * HID];  // 32 MB
__device__ unsigned short g_hlo[(size_t)NPAIR * HID];  // 32 MB

// ============ PTX helpers (sm_80-level PTX; target is plain sm_100) ============
__device__ __forceinline__ uint32_t smem_u32(const void* p) {
    uint32_t a;
    asm("{ .reg .u64 t; cvta.to.shared.u64 t, %1; cvt.u32.u64 %0, t; }" : "=r"(a) : "l"(p));
    return a;
}
__device__ __forceinline__ void cp16(uint32_t dst, const void* src) {
    asm volatile("cp.async.cg.shared.global [%0], [%1], 16;" :: "r"(dst), "l"(src));
}
__device__ __forceinline__ void cp_commit() {
    asm volatile("cp.async.commit_group;" ::: "memory");
}
__device__ __forceinline__ void cp_wait_all() {
    asm volatile("cp.async.wait_group 0;" ::: "memory");
}
__device__ __forceinline__ void ldsm4(uint32_t* r, uint32_t addr) {
    asm volatile("ldmatrix.sync.aligned.m8n8.x4.shared.b16 {%0,%1,%2,%3}, [%4];"
                 : "=r"(r[0]), "=r"(r[1]), "=r"(r[2]), "=r"(r[3]) : "r"(addr));
}
__device__ __forceinline__ void ldsm4t(uint32_t* r, uint32_t addr) {
    asm volatile("ldmatrix.sync.aligned.m8n8.x4.trans.shared.b16 {%0,%1,%2,%3}, [%4];"
                 : "=r"(r[0]), "=r"(r[1]), "=r"(r[2]), "=r"(r[3]) : "r"(addr));
}
__device__ __forceinline__ void mma16816(float* d, const uint32_t* a, const uint32_t* b) {
    asm volatile(
        "mma.sync.aligned.m16n8k16.row.col.f32.bf16.bf16.f32 "
        "{%0,%1,%2,%3}, {%4,%5,%6,%7}, {%8,%9}, {%0,%1,%2,%3};"
        : "+f"(d[0]), "+f"(d[1]), "+f"(d[2]), "+f"(d[3])
        : "r"(a[0]), "r"(a[1]), "r"(a[2]), "r"(a[3]), "r"(b[0]), "r"(b[1]));
}
__device__ __forceinline__ void split2(float v, unsigned short& hi, unsigned short& lo) {
    __nv_bfloat16 h = __float2bfloat16(v);
    hi = __bfloat16_as_ushort(h);
    lo = __bfloat16_as_ushort(__float2bfloat16(v - __bfloat162float(h)));
}
__device__ __forceinline__ void split4(float4 v, uint2& ph, uint2& pl) {
    unsigned short h0, l0, h1, l1, h2, l2, h3, l3;
    split2(v.x, h0, l0); split2(v.y, h1, l1); split2(v.z, h2, l2); split2(v.w, h3, l3);
    ph = make_uint2((uint32_t)h0 | ((uint32_t)h1 << 16), (uint32_t)h2 | ((uint32_t)h3 << 16));
    pl = make_uint2((uint32_t)l0 | ((uint32_t)l1 << 16), (uint32_t)l2 | ((uint32_t)l3 << 16));
}

// ============ routing ============
__global__ void zero_counts_kernel() {
    if (threadIdx.x < NEXP) g_counts[threadIdx.x] = 0;
}

__global__ void gating_kernel(const float* __restrict__ x,
                              const float* __restrict__ Wg,
                              const int* __restrict__ task_ptr) {
    int gw   = (blockIdx.x * blockDim.x + threadIdx.x) >> 5;
    int lane = threadIdx.x & 31;
    if (gw >= NTOK) return;

    const int task = task_ptr[0];
    const float* xr = x + (size_t)gw * DIM;
    const float* wg = Wg + (size_t)task * (DIM * NEXP);

    float s0 = 0.f, s1 = 0.f, s2 = 0.f, s3 = 0.f, s4 = 0.f, s5 = 0.f, s6 = 0.f, s7 = 0.f;
    for (int d = lane; d < DIM; d += 32) {
        float xv = xr[d];
        const float4* w4 = reinterpret_cast<const float4*>(wg + (size_t)d * NEXP);
        float4 a = w4[0];
        float4 b = w4[1];
        s0 += xv * a.x; s1 += xv * a.y; s2 += xv * a.z; s3 += xv * a.w;
        s4 += xv * b.x; s5 += xv * b.y; s6 += xv * b.z; s7 += xv * b.w;
    }
    #pragma unroll
    for (int off = 16; off > 0; off >>= 1) {
        s0 += __shfl_down_sync(0xffffffffu, s0, off);
        s1 += __shfl_down_sync(0xffffffffu, s1, off);
        s2 += __shfl_down_sync(0xffffffffu, s2, off);
        s3 += __shfl_down_sync(0xffffffffu, s3, off);
        s4 += __shfl_down_sync(0xffffffffu, s4, off);
        s5 += __shfl_down_sync(0xffffffffu, s5, off);
        s6 += __shfl_down_sync(0xffffffffu, s6, off);
        s7 += __shfl_down_sync(0xffffffffu, s7, off);
    }
    if (lane == 0) {
        float l[NEXP] = {s0, s1, s2, s3, s4, s5, s6, s7};
        float mx = l[0];
        #pragma unroll
        for (int e = 1; e < NEXP; e++) mx = fmaxf(mx, l[e]);
        float p[NEXP];
        float sum = 0.f;
        #pragma unroll
        for (int e = 0; e < NEXP; e++) { p[e] = expf(l[e] - mx); sum += p[e]; }
        float inv = 1.0f / sum;

        int i1 = 0;
        #pragma unroll
        for (int e = 1; e < NEXP; e++) if (l[e] > l[i1]) i1 = e;
        int i2 = (i1 == 0) ? 1 : 0;
        #pragma unroll
        for (int e = 0; e < NEXP; e++) if (e != i1 && l[e] > l[i2]) i2 = e;

        int pos1 = atomicAdd(&g_counts[i1], 1);
        g_tokens  [i1 * NTOK + pos1] = gw;
        g_slotgate[i1 * NTOK + pos1] = p[i1] * inv;
        int pos2 = atomicAdd(&g_counts[i2], 1);
        g_tokens  [i2 * NTOK + pos2] = gw;
        g_slotgate[i2 * NTOK + pos2] = p[i2] * inv;
    }
}

__global__ void scan_kernel() {
    if (threadIdx.x == 0) {
        int o = 0;
        #pragma unroll
        for (int e = 0; e < NEXP; e++) { g_offsets[e] = o; o += g_counts[e]; }
        g_offsets[NEXP] = o;
    }
}

// ============ mma.sync grouped GEMM (bf16x3 split, double-buffered) ============
// 128x128 tile, BK=32, 256 threads = 8 warps (4 m x 2 n).
// A SMEM: [128][32] bf16, 80B pitch  -> non-trans ldmatrix
// B SMEM: [32][128] bf16, 272B pitch -> trans ldmatrix
#define BK     32
#define ROWA   80
#define ROWB   272
#define A_TILE (128 * ROWA)                // 10240
#define B_TILE (BK * ROWB)                 // 8704
#define STAGE_BYTES (2 * A_TILE + 2 * B_TILE)   // 37888
#define GEMM_SMEM   (2 * STAGE_BYTES)           // 75776

template<int KLEN, bool GELU>
__global__ __launch_bounds__(256, 1)
void moe_gemm_kernel(const float* __restrict__ x,
                     const float* __restrict__ W,
                     const float* __restrict__ bias,
                     float* __restrict__ y,
                     int NTOT) {
    const int e      = blockIdx.z;
    const int count  = g_counts[e];
    const int mStart = blockIdx.x * 128;
    if (mStart >= count) return;
    const int nStart = blockIdx.y * 128;
    const int hBase  = g_offsets[e];

    extern __shared__ char smem[];

    const int tid  = threadIdx.x;
    const int wid  = tid >> 5;
    const int lane = tid & 31;
    const int wm   = wid & 3;
    const int wn   = wid >> 2;

    const float* Wb = W + (size_t)e * KLEN * NTOT;
    const int* toks = g_tokens + e * NTOK;

    float4 areg[4];   // ffn1: x fp32 chunks
    float4 breg[4];   // W fp32 chunks

    // ffn2: A tiles (pre-split h) go straight gmem->smem via cp.async
    auto issue_cpA = [&](int k0, char* stg) {
        #pragma unroll
        for (int j = 0; j < 4; j++) {
            int id  = tid + 256 * j;
            int arr = id >> 9;               // 0: hi, 1: lo
            int cid = id & 511;
            int r   = cid >> 2;
            int c   = cid & 3;
            int gm  = mStart + r;
            if (gm >= count) gm = count - 1;
            const unsigned short* src = (arr ? g_hlo : g_hhi) + (size_t)(hBase + gm) * HID + k0 + c * 8;
            cp16(smem_u32(stg + arr * A_TILE + r * ROWA + c * 16), src);
        }
        cp_commit();
    };

    auto load_regs = [&](int k0) {
        if (GELU) {
            #pragma unroll
            for (int j = 0; j < 4; j++) {
                int id = tid + 256 * j;
                int r  = id >> 3;
                int c4 = id & 7;
                int gm = mStart + r;
                if (gm >= count) gm = count - 1;
                int tok = toks[gm];
                areg[j] = *reinterpret_cast<const float4*>(x + (size_t)tok * DIM + k0 + c4 * 4);
            }
        }
        #pragma unroll
        for (int j = 0; j < 4; j++) {
            int id = tid + 256 * j;
            int kr = id >> 5;
            int c4 = id & 31;
            breg[j] = *reinterpret_cast<const float4*>(Wb + (size_t)(k0 + kr) * NTOT + nStart + c4 * 4);
        }
    };

    auto store_stage = [&](char* stg) {
        if (GELU) {
            #pragma unroll
            for (int j = 0; j < 4; j++) {
                int id = tid + 256 * j;
                int r  = id >> 3;
                int c4 = id & 7;
                uint2 ph, pl;
                split4(areg[j], ph, pl);
                *reinterpret_cast<uint2*>(stg + r * ROWA + c4 * 8) = ph;
                *reinterpret_cast<uint2*>(stg + A_TILE + r * ROWA + c4 * 8) = pl;
            }
        }
        #pragma unroll
        for (int j = 0; j < 4; j++) {
            int id = tid + 256 * j;
            int kr = id >> 5;
            int c4 = id & 31;
            uint2 ph, pl;
            split4(breg[j], ph, pl);
            *reinterpret_cast<uint2*>(stg + 2 * A_TILE + kr * ROWB + c4 * 8) = ph;
            *reinterpret_cast<uint2*>(stg + 2 * A_TILE + B_TILE + kr * ROWB + c4 * 8) = pl;
        }
    };

    float acc[2][8][4];
    #pragma unroll
    for (int i = 0; i < 2; i++)
        #pragma unroll
        for (int j = 0; j < 8; j++)
            #pragma unroll
            for (int q = 0; q < 4; q++) acc[i][j][q] = 0.f;

    constexpr int NC = KLEN / BK;

    // prologue: fill stage 0
    if (!GELU) issue_cpA(0, smem);
    load_regs(0);
    store_stage(smem);
    if (!GELU) cp_wait_all();
    __syncthreads();

    for (int k = 0; k < NC; k++) {
        char* cur = smem + (k & 1) * STAGE_BYTES;
        char* nxt = smem + ((k + 1) & 1) * STAGE_BYTES;
        const uint32_t sAhi = smem_u32(cur);
        const uint32_t sAlo = sAhi + A_TILE;
        const uint32_t sBhi = sAlo + A_TILE;
        const uint32_t sBlo = sBhi + B_TILE;

        if (k + 1 < NC) {
            if (!GELU) issue_cpA((k + 1) * BK, nxt);
            load_regs((k + 1) * BK);           // LDGs in flight under the MMAs
        }

        #pragma unroll
        for (int kk = 0; kk < 2; kk++) {
            const int kof = kk * 16;
            uint32_t ah[2][4], al[2][4];
            #pragma unroll
            for (int mt = 0; mt < 2; mt++) {
                uint32_t off = (uint32_t)((wm * 32 + mt * 16 + (lane & 15)) * ROWA
                                          + (kof + ((lane & 16) ? 8 : 0)) * 2);
                ldsm4(ah[mt], sAhi + off);
                ldsm4(al[mt], sAlo + off);
            }
            #pragma unroll
            for (int p = 0; p < 4; p++) {
                int nb = wn * 64 + p * 16;
                int krow = kof + ((lane & 8) ? 8 : 0) + (lane & 7);
                int ncol = nb + ((lane & 16) ? 8 : 0);
                uint32_t boff = (uint32_t)(krow * ROWB + ncol * 2);
                uint32_t bh[4], bl[4];
                ldsm4t(bh, sBhi + boff);
                ldsm4t(bl, sBlo + boff);
                #pragma unroll
                for (int t = 0; t < 2; t++) {
                    uint32_t bhf[2] = {bh[2 * t], bh[2 * t + 1]};
                    uint32_t blf[2] = {bl[2 * t], bl[2 * t + 1]};
                    #pragma unroll
                    for (int mt = 0; mt < 2; mt++) {
                        float* d = acc[mt][2 * p + t];
                        mma16816(d, ah[mt], bhf);
                        mma16816(d, ah[mt], blf);
                        mma16816(d, al[mt], bhf);
                    }
                }
            }
        }

        if (k + 1 < NC) {
            store_stage(nxt);
            if (!GELU) cp_wait_all();
        }
        __syncthreads();
    }

    // ---- epilogue ----
    const int r0 = lane >> 2;
    const int c0 = 2 * (lane & 3);
    const float* gates = g_slotgate + e * NTOK;
    #pragma unroll
    for (int mt = 0; mt < 2; mt++) {
        #pragma unroll
        for (int nt = 0; nt < 8; nt++) {
            const float* d = acc[mt][nt];
            int lrow = mStart + wm * 32 + mt * 16 + r0;
            int col  = nStart + wn * 64 + nt * 8 + c0;
            float bs0 = bias[(size_t)e * NTOT + col];
            float bs1 = bias[(size_t)e * NTOT + col + 1];
            #pragma unroll
            for (int h = 0; h < 2; h++) {
                int rr = lrow + h * 8;
                if (rr >= count) continue;
                float v0 = d[2 * h + 0] + bs0;
                float v1 = d[2 * h + 1] + bs1;
                if (GELU) {
                    v0 = 0.5f * v0 * (1.0f + erff(v0 * 0.70710678118654752f));
                    v1 = 0.5f * v1 * (1.0f + erff(v1 * 0.70710678118654752f));
                    unsigned short h0, l0, h1, l1;
                    split2(v0, h0, l0);
                    split2(v1, h1, l1);
                    size_t ob = (size_t)(hBase + rr) * HID + col;
                    *reinterpret_cast<uint32_t*>(g_hhi + ob) = (uint32_t)h0 | ((uint32_t)h1 << 16);
                    *reinterpret_cast<uint32_t*>(g_hlo + ob) = (uint32_t)l0 | ((uint32_t)l1 << 16);
                } else {
                    int   tok  = toks[rr];
                    float gate = gates[rr];
                    float* yr = y + (size_t)tok * DIM + col;
                    atomicAdd(&yr[0], gate * v0);
                    atomicAdd(&yr[1], gate * v1);
                }
            }
        }
    }
}

// ============ launch ============
extern "C" void kernel_launch(void* const* d_in, const int* in_sizes, int n_in,
                              void* d_out, int out_size) {
    const float* x    = (const float*)d_in[0];
    const float* Wg   = (const float*)d_in[1];
    const float* W1   = (const float*)d_in[2];
    const float* b1   = (const float*)d_in[3];
    const float* W2   = (const float*)d_in[4];
    const float* b2   = (const float*)d_in[5];
    const int*   task = (const int*)  d_in[6];
    float* y = (float*)d_out;

    // Not stream ops; called unconditionally every time (no static guards).
    cudaFuncSetAttribute(moe_gemm_kernel<DIM, true>,
                         cudaFuncAttributeMaxDynamicSharedMemorySize, GEMM_SMEM);
    cudaFuncSetAttribute(moe_gemm_kernel<HID, false>,
                         cudaFuncAttributeMaxDynamicSharedMemorySize, GEMM_SMEM);

    cudaMemsetAsync(d_out, 0, (size_t)out_size * sizeof(float), 0);

    zero_counts_kernel<<<1, 32>>>();
    gating_kernel<<<(NTOK * 32 + 255) / 256, 256>>>(x, Wg, task);
    scan_kernel<<<1, 32>>>();

    // ffn1: h = gelu(x @ W1 + b1) -> bf16 hi/lo
    moe_gemm_kernel<DIM, true><<<dim3(NTOK / 128, HID / 128, NEXP), 256, GEMM_SMEM>>>(x, W1, b1, y, HID);
    // ffn2: y += gate * (h @ W2 + b2)
    moe_gemm_kernel<HID, false><<<dim3(NTOK / 128, DIM / 128, NEXP), 256, GEMM_SMEM>>>(x, W2, b2, y, DIM);
}

// round 10
// speedup vs baseline: 2.2652x; 1.0342x over previous
#include <cuda_runtime.h>
#include <cuda_bf16.h>
#include <math.h>
#include <stdint.h>

#define NTOK 4096
#define DIM  1024
#define HID  2048
#define NEXP 8
#define KSEL 2
#define NPAIR (NTOK * KSEL)

// ============ static scratch: ~64 MB ============
__device__ int   g_counts[NEXP];
__device__ int   g_offsets[NEXP + 1];
__device__ int   g_tokens[NEXP * NTOK];
__device__ float g_slotgate[NEXP * NTOK];
__device__ unsigned short g_hhi[(size_t)NPAIR * HID];
__device__ unsigned short g_hlo[(size_t)NPAIR * HID];

// ============ PTX helpers (sm_80-level PTX; target is plain sm_100) ============
__device__ __forceinline__ uint32_t smem_u32(const void* p) {
    uint32_t a;
    asm("{ .reg .u64 t; cvta.to.shared.u64 t, %1; cvt.u32.u64 %0, t; }" : "=r"(a) : "l"(p));
    return a;
}
__device__ __forceinline__ void cp16(uint32_t dst, const void* src) {
    asm volatile("cp.async.cg.shared.global [%0], [%1], 16;" :: "r"(dst), "l"(src));
}
__device__ __forceinline__ void cp_commit() {
    asm volatile("cp.async.commit_group;" ::: "memory");
}
__device__ __forceinline__ void cp_wait_all() {
    asm volatile("cp.async.wait_group 0;" ::: "memory");
}
__device__ __forceinline__ void ldsm4(uint32_t* r, uint32_t addr) {
    asm volatile("ldmatrix.sync.aligned.m8n8.x4.shared.b16 {%0,%1,%2,%3}, [%4];"
                 : "=r"(r[0]), "=r"(r[1]), "=r"(r[2]), "=r"(r[3]) : "r"(addr));
}
__device__ __forceinline__ void ldsm4t(uint32_t* r, uint32_t addr) {
    asm volatile("ldmatrix.sync.aligned.m8n8.x4.trans.shared.b16 {%0,%1,%2,%3}, [%4];"
                 : "=r"(r[0]), "=r"(r[1]), "=r"(r[2]), "=r"(r[3]) : "r"(addr));
}
__device__ __forceinline__ void mma16816(float* d, const uint32_t* a, const uint32_t* b) {
    asm volatile(
        "mma.sync.aligned.m16n8k16.row.col.f32.bf16.bf16.f32 "
        "{%0,%1,%2,%3}, {%4,%5,%6,%7}, {%8,%9}, {%0,%1,%2,%3};"
        : "+f"(d[0]), "+f"(d[1]), "+f"(d[2]), "+f"(d[3])
        : "r"(a[0]), "r"(a[1]), "r"(a[2]), "r"(a[3]), "r"(b[0]), "r"(b[1]));
}
__device__ __forceinline__ void split2(float v, unsigned short& hi, unsigned short& lo) {
    __nv_bfloat16 h = __float2bfloat16(v);
    hi = __bfloat16_as_ushort(h);
    lo = __bfloat16_as_ushort(__float2bfloat16(v - __bfloat162float(h)));
}
__device__ __forceinline__ void split4(float4 v, uint2& ph, uint2& pl) {
    unsigned short h0, l0, h1, l1, h2, l2, h3, l3;
    split2(v.x, h0, l0); split2(v.y, h1, l1); split2(v.z, h2, l2); split2(v.w, h3, l3);
    ph = make_uint2((uint32_t)h0 | ((uint32_t)h1 << 16), (uint32_t)h2 | ((uint32_t)h3 << 16));
    pl = make_uint2((uint32_t)l0 | ((uint32_t)l1 << 16), (uint32_t)l2 | ((uint32_t)l3 << 16));
}

// ============ routing ============
__global__ void zero_counts_kernel() {
    if (threadIdx.x < NEXP) g_counts[threadIdx.x] = 0;
}

__global__ void gating_kernel(const float* __restrict__ x,
                              const float* __restrict__ Wg,
                              const int* __restrict__ task_ptr) {
    int gw   = (blockIdx.x * blockDim.x + threadIdx.x) >> 5;
    int lane = threadIdx.x & 31;
    if (gw >= NTOK) return;

    const int task = task_ptr[0];
    const float* xr = x + (size_t)gw * DIM;
    const float* wg = Wg + (size_t)task * (DIM * NEXP);

    float s0 = 0.f, s1 = 0.f, s2 = 0.f, s3 = 0.f, s4 = 0.f, s5 = 0.f, s6 = 0.f, s7 = 0.f;
    for (int d = lane; d < DIM; d += 32) {
        float xv = xr[d];
        const float4* w4 = reinterpret_cast<const float4*>(wg + (size_t)d * NEXP);
        float4 a = w4[0];
        float4 b = w4[1];
        s0 += xv * a.x; s1 += xv * a.y; s2 += xv * a.z; s3 += xv * a.w;
        s4 += xv * b.x; s5 += xv * b.y; s6 += xv * b.z; s7 += xv * b.w;
    }
    #pragma unroll
    for (int off = 16; off > 0; off >>= 1) {
        s0 += __shfl_down_sync(0xffffffffu, s0, off);
        s1 += __shfl_down_sync(0xffffffffu, s1, off);
        s2 += __shfl_down_sync(0xffffffffu, s2, off);
        s3 += __shfl_down_sync(0xffffffffu, s3, off);
        s4 += __shfl_down_sync(0xffffffffu, s4, off);
        s5 += __shfl_down_sync(0xffffffffu, s5, off);
        s6 += __shfl_down_sync(0xffffffffu, s6, off);
        s7 += __shfl_down_sync(0xffffffffu, s7, off);
    }
    if (lane == 0) {
        float l[NEXP] = {s0, s1, s2, s3, s4, s5, s6, s7};
        float mx = l[0];
        #pragma unroll
        for (int e = 1; e < NEXP; e++) mx = fmaxf(mx, l[e]);
        float p[NEXP];
        float sum = 0.f;
        #pragma unroll
        for (int e = 0; e < NEXP; e++) { p[e] = expf(l[e] - mx); sum += p[e]; }
        float inv = 1.0f / sum;

        int i1 = 0;
        #pragma unroll
        for (int e = 1; e < NEXP; e++) if (l[e] > l[i1]) i1 = e;
        int i2 = (i1 == 0) ? 1 : 0;
        #pragma unroll
        for (int e = 0; e < NEXP; e++) if (e != i1 && l[e] > l[i2]) i2 = e;

        int pos1 = atomicAdd(&g_counts[i1], 1);
        g_tokens  [i1 * NTOK + pos1] = gw;
        g_slotgate[i1 * NTOK + pos1] = p[i1] * inv;
        int pos2 = atomicAdd(&g_counts[i2], 1);
        g_tokens  [i2 * NTOK + pos2] = gw;
        g_slotgate[i2 * NTOK + pos2] = p[i2] * inv;
    }
}

__global__ void scan_kernel() {
    if (threadIdx.x == 0) {
        int o = 0;
        #pragma unroll
        for (int e = 0; e < NEXP; e++) { g_offsets[e] = o; o += g_counts[e]; }
        g_offsets[NEXP] = o;
    }
}

// ============ mma.sync grouped GEMM (bf16x3 split, 512 threads, pass-major) ============
// 128x128 tile, BK=32, 512 threads = 16 warps (4 m x 4 n); warp tile 32x32.
#define BK     32
#define NTHR   512
#define ROWA   80
#define ROWB   272
#define A_TILE (128 * ROWA)                     // 10240
#define B_TILE (BK * ROWB)                      // 8704
#define STAGE_BYTES (2 * A_TILE + 2 * B_TILE)   // 37888
#define GEMM_SMEM   (2 * STAGE_BYTES)           // 75776

template<int KLEN, bool GELU>
__global__ __launch_bounds__(NTHR, 1)
void moe_gemm_kernel(const float* __restrict__ x,
                     const float* __restrict__ W,
                     const float* __restrict__ bias,
                     float* __restrict__ y,
                     int NTOT) {
    const int e      = blockIdx.z;
    const int count  = g_counts[e];
    const int mStart = blockIdx.x * 128;
    if (mStart >= count) return;
    const int nStart = blockIdx.y * 128;
    const int hBase  = g_offsets[e];

    extern __shared__ char smem[];

    const int tid  = threadIdx.x;
    const int wid  = tid >> 5;
    const int lane = tid & 31;
    const int wm   = wid & 3;        // 4 warps along M (32 rows)
    const int wn   = wid >> 2;       // 4 warps along N (32 cols)

    const float* Wb = W + (size_t)e * KLEN * NTOT;
    const int* toks = g_tokens + e * NTOK;

    float4 areg[2];
    float4 breg[2];

    // ffn2: A tiles (pre-split h) straight gmem->smem via cp.async (1024 chunks / 512 thr)
    auto issue_cpA = [&](int k0, char* stg) {
        #pragma unroll
        for (int j = 0; j < 2; j++) {
            int id  = tid + NTHR * j;
            int arr = id >> 9;               // 0: hi, 1: lo
            int cid = id & 511;
            int r   = cid >> 2;
            int c   = cid & 3;
            int gm  = mStart + r;
            if (gm >= count) gm = count - 1;
            const unsigned short* src = (arr ? g_hlo : g_hhi) + (size_t)(hBase + gm) * HID + k0 + c * 8;
            cp16(smem_u32(stg + arr * A_TILE + r * ROWA + c * 16), src);
        }
        cp_commit();
    };

    auto load_regs = [&](int k0) {
        if (GELU) {
            #pragma unroll
            for (int j = 0; j < 2; j++) {
                int id = tid + NTHR * j;
                int r  = id >> 3;
                int c4 = id & 7;
                int gm = mStart + r;
                if (gm >= count) gm = count - 1;
                int tok = toks[gm];
                areg[j] = *reinterpret_cast<const float4*>(x + (size_t)tok * DIM + k0 + c4 * 4);
            }
        }
        #pragma unroll
        for (int j = 0; j < 2; j++) {
            int id = tid + NTHR * j;
            int kr = id >> 5;
            int c4 = id & 31;
            breg[j] = *reinterpret_cast<const float4*>(Wb + (size_t)(k0 + kr) * NTOT + nStart + c4 * 4);
        }
    };

    auto store_stage = [&](char* stg) {
        if (GELU) {
            #pragma unroll
            for (int j = 0; j < 2; j++) {
                int id = tid + NTHR * j;
                int r  = id >> 3;
                int c4 = id & 7;
                uint2 ph, pl;
                split4(areg[j], ph, pl);
                *reinterpret_cast<uint2*>(stg + r * ROWA + c4 * 8) = ph;
                *reinterpret_cast<uint2*>(stg + A_TILE + r * ROWA + c4 * 8) = pl;
            }
        }
        #pragma unroll
        for (int j = 0; j < 2; j++) {
            int id = tid + NTHR * j;
            int kr = id >> 5;
            int c4 = id & 31;
            uint2 ph, pl;
            split4(breg[j], ph, pl);
            *reinterpret_cast<uint2*>(stg + 2 * A_TILE + kr * ROWB + c4 * 8) = ph;
            *reinterpret_cast<uint2*>(stg + 2 * A_TILE + B_TILE + kr * ROWB + c4 * 8) = pl;
        }
    };

    // warp tile 32x32: acc[mt][p*2+t][4]
    float acc[2][4][4];
    #pragma unroll
    for (int i = 0; i < 2; i++)
        #pragma unroll
        for (int j = 0; j < 4; j++)
            #pragma unroll
            for (int q = 0; q < 4; q++) acc[i][j][q] = 0.f;

    constexpr int NC = KLEN / BK;

    if (!GELU) issue_cpA(0, smem);
    load_regs(0);
    store_stage(smem);
    if (!GELU) cp_wait_all();
    __syncthreads();

    for (int k = 0; k < NC; k++) {
        char* cur = smem + (k & 1) * STAGE_BYTES;
        char* nxt = smem + ((k + 1) & 1) * STAGE_BYTES;
        const uint32_t sAhi = smem_u32(cur);
        const uint32_t sAlo = sAhi + A_TILE;
        const uint32_t sBhi = sAlo + A_TILE;
        const uint32_t sBlo = sBhi + B_TILE;

        if (k + 1 < NC) {
            if (!GELU) issue_cpA((k + 1) * BK, nxt);
            load_regs((k + 1) * BK);
        }

        #pragma unroll
        for (int kk = 0; kk < 2; kk++) {
            const int kof = kk * 16;

            // A fragments: 2 m16 tiles (hi & lo)
            uint32_t ah[2][4], al[2][4];
            #pragma unroll
            for (int mt = 0; mt < 2; mt++) {
                uint32_t off = (uint32_t)((wm * 32 + mt * 16 + (lane & 15)) * ROWA
                                          + (kof + ((lane & 16) ? 8 : 0)) * 2);
                ldsm4(ah[mt], sAhi + off);
                ldsm4(al[mt], sAlo + off);
            }
            // B fragments: 2 n16 groups (each = two n8 tiles), hi & lo
            uint32_t bh[2][4], bl[2][4];
            #pragma unroll
            for (int p = 0; p < 2; p++) {
                int krow = kof + ((lane & 8) ? 8 : 0) + (lane & 7);
                int ncol = wn * 32 + p * 16 + ((lane & 16) ? 8 : 0);
                uint32_t boff = (uint32_t)(krow * ROWB + ncol * 2);
                ldsm4t(bh[p], sBhi + boff);
                ldsm4t(bl[p], sBlo + boff);
            }

            // pass-major: dependent MMAs on the same accumulator are 8 apart
            #pragma unroll
            for (int mt = 0; mt < 2; mt++)
                #pragma unroll
                for (int p = 0; p < 2; p++)
                    #pragma unroll
                    for (int t = 0; t < 2; t++)
                        mma16816(acc[mt][2 * p + t], ah[mt], &bh[p][2 * t]);   // hi*hi
            #pragma unroll
            for (int mt = 0; mt < 2; mt++)
                #pragma unroll
                for (int p = 0; p < 2; p++)
                    #pragma unroll
                    for (int t = 0; t < 2; t++)
                        mma16816(acc[mt][2 * p + t], ah[mt], &bl[p][2 * t]);   // hi*lo
            #pragma unroll
            for (int mt = 0; mt < 2; mt++)
                #pragma unroll
                for (int p = 0; p < 2; p++)
                    #pragma unroll
                    for (int t = 0; t < 2; t++)
                        mma16816(acc[mt][2 * p + t], al[mt], &bh[p][2 * t]);   // lo*hi
        }

        if (k + 1 < NC) {
            store_stage(nxt);
            if (!GELU) cp_wait_all();
        }
        __syncthreads();
    }

    // ---- epilogue: warp 32x32 block ----
    const int r0 = lane >> 2;
    const int c0 = 2 * (lane & 3);
    const float* gates = g_slotgate + e * NTOK;
    #pragma unroll
    for (int mt = 0; mt < 2; mt++) {
        #pragma unroll
        for (int nt = 0; nt < 4; nt++) {
            const float* d = acc[mt][nt];
            int lrow = mStart + wm * 32 + mt * 16 + r0;
            int col  = nStart + wn * 32 + nt * 8 + c0;
            float bs0 = bias[(size_t)e * NTOT + col];
            float bs1 = bias[(size_t)e * NTOT + col + 1];
            #pragma unroll
            for (int h = 0; h < 2; h++) {
                int rr = lrow + h * 8;
                if (rr >= count) continue;
                float v0 = d[2 * h + 0] + bs0;
                float v1 = d[2 * h + 1] + bs1;
                if (GELU) {
                    v0 = 0.5f * v0 * (1.0f + erff(v0 * 0.70710678118654752f));
                    v1 = 0.5f * v1 * (1.0f + erff(v1 * 0.70710678118654752f));
                    unsigned short h0, l0, h1, l1;
                    split2(v0, h0, l0);
                    split2(v1, h1, l1);
                    size_t ob = (size_t)(hBase + rr) * HID + col;
                    *reinterpret_cast<uint32_t*>(g_hhi + ob) = (uint32_t)h0 | ((uint32_t)h1 << 16);
                    *reinterpret_cast<uint32_t*>(g_hlo + ob) = (uint32_t)l0 | ((uint32_t)l1 << 16);
                } else {
                    int   tok  = toks[rr];
                    float gate = gates[rr];
                    float* yr = y + (size_t)tok * DIM + col;
                    atomicAdd(&yr[0], gate * v0);
                    atomicAdd(&yr[1], gate * v1);
                }
            }
        }
    }
}

// ============ launch ============
extern "C" void kernel_launch(void* const* d_in, const int* in_sizes, int n_in,
                              void* d_out, int out_size) {
    const float* x    = (const float*)d_in[0];
    const float* Wg   = (const float*)d_in[1];
    const float* W1   = (const float*)d_in[2];
    const float* b1   = (const float*)d_in[3];
    const float* W2   = (const float*)d_in[4];
    const float* b2   = (const float*)d_in[5];
    const int*   task = (const int*)  d_in[6];
    float* y = (float*)d_out;

    cudaFuncSetAttribute(moe_gemm_kernel<DIM, true>,
                         cudaFuncAttributeMaxDynamicSharedMemorySize, GEMM_SMEM);
    cudaFuncSetAttribute(moe_gemm_kernel<HID, false>,
                         cudaFuncAttributeMaxDynamicSharedMemorySize, GEMM_SMEM);

    cudaMemsetAsync(d_out, 0, (size_t)out_size * sizeof(float), 0);

    zero_counts_kernel<<<1, 32>>>();
    gating_kernel<<<(NTOK * 32 + 255) / 256, 256>>>(x, Wg, task);
    scan_kernel<<<1, 32>>>();

    // ffn1: h = gelu(x @ W1 + b1) -> bf16 hi/lo
    moe_gemm_kernel<DIM, true><<<dim3(NTOK / 128, HID / 128, NEXP), NTHR, GEMM_SMEM>>>(x, W1, b1, y, HID);
    // ffn2: y += gate * (h @ W2 + b2)
    moe_gemm_kernel<HID, false><<<dim3(NTOK / 128, DIM / 128, NEXP), NTHR, GEMM_SMEM>>>(x, W2, b2, y, DIM);
}

// round 12
// speedup vs baseline: 3.0244x; 1.3352x over previous
#include <cuda_runtime.h>
#include <cuda_fp16.h>
#include <math.h>
#include <stdint.h>

#define NTOK 4096
#define DIM  1024
#define HID  2048
#define NEXP 8
#define KSEL 2
#define NPAIR (NTOK * KSEL)

// ============ static scratch: ~64 MB ============
__device__ int   g_counts[NEXP];
__device__ int   g_offsets[NEXP + 1];
__device__ int   g_tokens[NEXP * NTOK];
__device__ float g_slotgate[NEXP * NTOK];
__device__ unsigned short g_hhi[(size_t)NPAIR * HID];   // fp16 hi of h
__device__ unsigned short g_hlo[(size_t)NPAIR * HID];   // fp16 lo of h

// ============ PTX helpers (sm_80-level PTX; target is plain sm_100) ============
__device__ __forceinline__ uint32_t smem_u32(const void* p) {
    uint32_t a;
    asm("{ .reg .u64 t; cvta.to.shared.u64 t, %1; cvt.u32.u64 %0, t; }" : "=r"(a) : "l"(p));
    return a;
}
__device__ __forceinline__ void cp16(uint32_t dst, const void* src) {
    asm volatile("cp.async.cg.shared.global [%0], [%1], 16;" :: "r"(dst), "l"(src));
}
__device__ __forceinline__ void cp_commit() {
    asm volatile("cp.async.commit_group;" ::: "memory");
}
__device__ __forceinline__ void cp_wait_all() {
    asm volatile("cp.async.wait_group 0;" ::: "memory");
}
__device__ __forceinline__ void ldsm4(uint32_t* r, uint32_t addr) {
    asm volatile("ldmatrix.sync.aligned.m8n8.x4.shared.b16 {%0,%1,%2,%3}, [%4];"
                 : "=r"(r[0]), "=r"(r[1]), "=r"(r[2]), "=r"(r[3]) : "r"(addr));
}
__device__ __forceinline__ void ldsm4t(uint32_t* r, uint32_t addr) {
    asm volatile("ldmatrix.sync.aligned.m8n8.x4.trans.shared.b16 {%0,%1,%2,%3}, [%4];"
                 : "=r"(r[0]), "=r"(r[1]), "=r"(r[2]), "=r"(r[3]) : "r"(addr));
}
__device__ __forceinline__ void mma16816h(float* d, const uint32_t* a, const uint32_t* b) {
    asm volatile(
        "mma.sync.aligned.m16n8k16.row.col.f32.f16.f16.f32 "
        "{%0,%1,%2,%3}, {%4,%5,%6,%7}, {%8,%9}, {%0,%1,%2,%3};"
        : "+f"(d[0]), "+f"(d[1]), "+f"(d[2]), "+f"(d[3])
        : "r"(a[0]), "r"(a[1]), "r"(a[2]), "r"(a[3]), "r"(b[0]), "r"(b[1]));
}
// fp16 split: hi = fp16(v), lo = fp16(v - hi)  (22-bit effective mantissa)
__device__ __forceinline__ void split2h(float v, unsigned short& hi, unsigned short& lo) {
    __half h = __float2half_rn(v);
    hi = __half_as_ushort(h);
    lo = __half_as_ushort(__float2half_rn(v - __half2float(h)));
}
__device__ __forceinline__ void split4h(float4 v, uint2& ph, uint2& pl) {
    unsigned short h0, l0, h1, l1, h2, l2, h3, l3;
    split2h(v.x, h0, l0); split2h(v.y, h1, l1); split2h(v.z, h2, l2); split2h(v.w, h3, l3);
    ph = make_uint2((uint32_t)h0 | ((uint32_t)h1 << 16), (uint32_t)h2 | ((uint32_t)h3 << 16));
    pl = make_uint2((uint32_t)l0 | ((uint32_t)l1 << 16), (uint32_t)l2 | ((uint32_t)l3 << 16));
}
// plain fp16 convert of float4 -> 4 packed halves
__device__ __forceinline__ uint2 cvt4h(float4 v) {
    __half2 a = __floats2half2_rn(v.x, v.y);
    __half2 b = __floats2half2_rn(v.z, v.w);
    return make_uint2(*reinterpret_cast<uint32_t*>(&a), *reinterpret_cast<uint32_t*>(&b));
}

// ============ routing ============
__global__ void zero_counts_kernel() {
    if (threadIdx.x < NEXP) g_counts[threadIdx.x] = 0;
}

__global__ void gating_kernel(const float* __restrict__ x,
                              const float* __restrict__ Wg,
                              const int* __restrict__ task_ptr) {
    int gw   = (blockIdx.x * blockDim.x + threadIdx.x) >> 5;
    int lane = threadIdx.x & 31;
    if (gw >= NTOK) return;

    const int task = task_ptr[0];
    const float* xr = x + (size_t)gw * DIM;
    const float* wg = Wg + (size_t)task * (DIM * NEXP);

    float s0 = 0.f, s1 = 0.f, s2 = 0.f, s3 = 0.f, s4 = 0.f, s5 = 0.f, s6 = 0.f, s7 = 0.f;
    for (int d = lane; d < DIM; d += 32) {
        float xv = xr[d];
        const float4* w4 = reinterpret_cast<const float4*>(wg + (size_t)d * NEXP);
        float4 a = w4[0];
        float4 b = w4[1];
        s0 += xv * a.x; s1 += xv * a.y; s2 += xv * a.z; s3 += xv * a.w;
        s4 += xv * b.x; s5 += xv * b.y; s6 += xv * b.z; s7 += xv * b.w;
    }
    #pragma unroll
    for (int off = 16; off > 0; off >>= 1) {
        s0 += __shfl_down_sync(0xffffffffu, s0, off);
        s1 += __shfl_down_sync(0xffffffffu, s1, off);
        s2 += __shfl_down_sync(0xffffffffu, s2, off);
        s3 += __shfl_down_sync(0xffffffffu, s3, off);
        s4 += __shfl_down_sync(0xffffffffu, s4, off);
        s5 += __shfl_down_sync(0xffffffffu, s5, off);
        s6 += __shfl_down_sync(0xffffffffu, s6, off);
        s7 += __shfl_down_sync(0xffffffffu, s7, off);
    }
    if (lane == 0) {
        float l[NEXP] = {s0, s1, s2, s3, s4, s5, s6, s7};
        float mx = l[0];
        #pragma unroll
        for (int e = 1; e < NEXP; e++) mx = fmaxf(mx, l[e]);
        float p[NEXP];
        float sum = 0.f;
        #pragma unroll
        for (int e = 0; e < NEXP; e++) { p[e] = expf(l[e] - mx); sum += p[e]; }
        float inv = 1.0f / sum;

        int i1 = 0;
        #pragma unroll
        for (int e = 1; e < NEXP; e++) if (l[e] > l[i1]) i1 = e;
        int i2 = (i1 == 0) ? 1 : 0;
        #pragma unroll
        for (int e = 0; e < NEXP; e++) if (e != i1 && l[e] > l[i2]) i2 = e;

        int pos1 = atomicAdd(&g_counts[i1], 1);
        g_tokens  [i1 * NTOK + pos1] = gw;
        g_slotgate[i1 * NTOK + pos1] = p[i1] * inv;
        int pos2 = atomicAdd(&g_counts[i2], 1);
        g_tokens  [i2 * NTOK + pos2] = gw;
        g_slotgate[i2 * NTOK + pos2] = p[i2] * inv;
    }
}

__global__ void scan_kernel() {
    if (threadIdx.x == 0) {
        int o = 0;
        #pragma unroll
        for (int e = 0; e < NEXP; e++) { g_offsets[e] = o; o += g_counts[e]; }
        g_offsets[NEXP] = o;
    }
}

// ============ mma.sync grouped GEMM (fp16 2-pass A-split, 512 threads) ============
// 128x128 tile, BK=32, 512 threads = 16 warps (4 m x 4 n); warp tile 32x32.
// SMEM: A-hi [128][32] fp16 80B pitch, A-lo same, B [32][128] fp16 272B pitch.
#define BK     32
#define NTHR   512
#define ROWA   80
#define ROWB   272
#define A_TILE (128 * ROWA)                     // 10240
#define B_TILE (BK * ROWB)                      // 8704
#define STAGE_BYTES (2 * A_TILE + B_TILE)       // 29184
#define GEMM_SMEM   (2 * STAGE_BYTES)           // 58368

template<int KLEN, bool GELU>
__global__ __launch_bounds__(NTHR, 1)
void moe_gemm_kernel(const float* __restrict__ x,
                     const float* __restrict__ W,
                     const float* __restrict__ bias,
                     float* __restrict__ y,
                     int NTOT) {
    const int e      = blockIdx.z;
    const int count  = g_counts[e];
    const int mStart = blockIdx.x * 128;
    if (mStart >= count) return;
    const int nStart = blockIdx.y * 128;
    const int hBase  = g_offsets[e];

    extern __shared__ char smem[];

    const int tid  = threadIdx.x;
    const int wid  = tid >> 5;
    const int lane = tid & 31;
    const int wm   = wid & 3;        // 4 warps along M (32 rows)
    const int wn   = wid >> 2;       // 4 warps along N (32 cols)

    const float* Wb = W + (size_t)e * KLEN * NTOT;
    const int* toks = g_tokens + e * NTOK;

    float4 areg[2];
    float4 breg[2];

    // ffn2: A tiles (pre-split fp16 h) straight gmem->smem via cp.async
    auto issue_cpA = [&](int k0, char* stg) {
        #pragma unroll
        for (int j = 0; j < 2; j++) {
            int id  = tid + NTHR * j;
            int arr = id >> 9;               // 0: hi, 1: lo
            int cid = id & 511;
            int r   = cid >> 2;
            int c   = cid & 3;
            int gm  = mStart + r;
            if (gm >= count) gm = count - 1;
            const unsigned short* src = (arr ? g_hlo : g_hhi) + (size_t)(hBase + gm) * HID + k0 + c * 8;
            cp16(smem_u32(stg + arr * A_TILE + r * ROWA + c * 16), src);
        }
        cp_commit();
    };

    auto load_regs = [&](int k0) {
        if (GELU) {
            #pragma unroll
            for (int j = 0; j < 2; j++) {
                int id = tid + NTHR * j;
                int r  = id >> 3;
                int c4 = id & 7;
                int gm = mStart + r;
                if (gm >= count) gm = count - 1;
                int tok = toks[gm];
                areg[j] = *reinterpret_cast<const float4*>(x + (size_t)tok * DIM + k0 + c4 * 4);
            }
        }
        #pragma unroll
        for (int j = 0; j < 2; j++) {
            int id = tid + NTHR * j;
            int kr = id >> 5;
            int c4 = id & 31;
            breg[j] = *reinterpret_cast<const float4*>(Wb + (size_t)(k0 + kr) * NTOT + nStart + c4 * 4);
        }
    };

    auto store_stage = [&](char* stg) {
        if (GELU) {
            #pragma unroll
            for (int j = 0; j < 2; j++) {
                int id = tid + NTHR * j;
                int r  = id >> 3;
                int c4 = id & 7;
                uint2 ph, pl;
                split4h(areg[j], ph, pl);
                *reinterpret_cast<uint2*>(stg + r * ROWA + c4 * 8) = ph;
                *reinterpret_cast<uint2*>(stg + A_TILE + r * ROWA + c4 * 8) = pl;
            }
        }
        #pragma unroll
        for (int j = 0; j < 2; j++) {
            int id = tid + NTHR * j;
            int kr = id >> 5;
            int c4 = id & 31;
            *reinterpret_cast<uint2*>(stg + 2 * A_TILE + kr * ROWB + c4 * 8) = cvt4h(breg[j]);
        }
    };

    // warp tile 32x32: acc[mt][p*2+t][4]
    float acc[2][4][4];
    #pragma unroll
    for (int i = 0; i < 2; i++)
        #pragma unroll
        for (int j = 0; j < 4; j++)
            #pragma unroll
            for (int q = 0; q < 4; q++) acc[i][j][q] = 0.f;

    constexpr int NC = KLEN / BK;

    if (!GELU) issue_cpA(0, smem);
    load_regs(0);
    store_stage(smem);
    if (!GELU) cp_wait_all();
    __syncthreads();

    for (int k = 0; k < NC; k++) {
        char* cur = smem + (k & 1) * STAGE_BYTES;
        char* nxt = smem + ((k + 1) & 1) * STAGE_BYTES;
        const uint32_t sAhi = smem_u32(cur);
        const uint32_t sAlo = sAhi + A_TILE;
        const uint32_t sB   = sAlo + A_TILE;

        if (k + 1 < NC) {
            if (!GELU) issue_cpA((k + 1) * BK, nxt);
            load_regs((k + 1) * BK);
        }

        #pragma unroll
        for (int kk = 0; kk < 2; kk++) {
            const int kof = kk * 16;

            uint32_t ah[2][4], al[2][4];
            #pragma unroll
            for (int mt = 0; mt < 2; mt++) {
                uint32_t off = (uint32_t)((wm * 32 + mt * 16 + (lane & 15)) * ROWA
                                          + (kof + ((lane & 16) ? 8 : 0)) * 2);
                ldsm4(ah[mt], sAhi + off);
                ldsm4(al[mt], sAlo + off);
            }
            uint32_t bb[2][4];
            #pragma unroll
            for (int p = 0; p < 2; p++) {
                int krow = kof + ((lane & 8) ? 8 : 0) + (lane & 7);
                int ncol = wn * 32 + p * 16 + ((lane & 16) ? 8 : 0);
                ldsm4t(bb[p], sB + (uint32_t)(krow * ROWB + ncol * 2));
            }

            // pass 1: Ahi * B
            #pragma unroll
            for (int mt = 0; mt < 2; mt++)
                #pragma unroll
                for (int p = 0; p < 2; p++)
                    #pragma unroll
                    for (int t = 0; t < 2; t++)
                        mma16816h(acc[mt][2 * p + t], ah[mt], &bb[p][2 * t]);
            // pass 2: Alo * B
            #pragma unroll
            for (int mt = 0; mt < 2; mt++)
                #pragma unroll
                for (int p = 0; p < 2; p++)
                    #pragma unroll
                    for (int t = 0; t < 2; t++)
                        mma16816h(acc[mt][2 * p + t], al[mt], &bb[p][2 * t]);
        }

        if (k + 1 < NC) {
            store_stage(nxt);
            if (!GELU) cp_wait_all();
        }
        __syncthreads();
    }

    // ---- epilogue: warp 32x32 block ----
    const int r0 = lane >> 2;
    const int c0 = 2 * (lane & 3);
    const float* gates = g_slotgate + e * NTOK;
    #pragma unroll
    for (int mt = 0; mt < 2; mt++) {
        #pragma unroll
        for (int nt = 0; nt < 4; nt++) {
            const float* d = acc[mt][nt];
            int lrow = mStart + wm * 32 + mt * 16 + r0;
            int col  = nStart + wn * 32 + nt * 8 + c0;
            float bs0 = bias[(size_t)e * NTOT + col];
            float bs1 = bias[(size_t)e * NTOT + col + 1];
            #pragma unroll
            for (int h = 0; h < 2; h++) {
                int rr = lrow + h * 8;
                if (rr >= count) continue;
                float v0 = d[2 * h + 0] + bs0;
                float v1 = d[2 * h + 1] + bs1;
                if (GELU) {
                    v0 = 0.5f * v0 * (1.0f + erff(v0 * 0.70710678118654752f));
                    v1 = 0.5f * v1 * (1.0f + erff(v1 * 0.70710678118654752f));
                    unsigned short h0, l0, h1, l1;
                    split2h(v0, h0, l0);
                    split2h(v1, h1, l1);
                    size_t ob = (size_t)(hBase + rr) * HID + col;
                    *reinterpret_cast<uint32_t*>(g_hhi + ob) = (uint32_t)h0 | ((uint32_t)h1 << 16);
                    *reinterpret_cast<uint32_t*>(g_hlo + ob) = (uint32_t)l0 | ((uint32_t)l1 << 16);
                } else {
                    int   tok  = toks[rr];
                    float gate = gates[rr];
                    float* yr = y + (size_t)tok * DIM + col;
                    atomicAdd(&yr[0], gate * v0);
                    atomicAdd(&yr[1], gate * v1);
                }
            }
        }
    }
}

// ============ launch ============
extern "C" void kernel_launch(void* const* d_in, const int* in_sizes, int n_in,
                              void* d_out, int out_size) {
    const float* x    = (const float*)d_in[0];
    const float* Wg   = (const float*)d_in[1];
    const float* W1   = (const float*)d_in[2];
    const float* b1   = (const float*)d_in[3];
    const float* W2   = (const float*)d_in[4];
    const float* b2   = (const float*)d_in[5];
    const int*   task = (const int*)  d_in[6];
    float* y = (float*)d_out;

    cudaFuncSetAttribute(moe_gemm_kernel<DIM, true>,
                         cudaFuncAttributeMaxDynamicSharedMemorySize, GEMM_SMEM);
    cudaFuncSetAttribute(moe_gemm_kernel<HID, false>,
                         cudaFuncAttributeMaxDynamicSharedMemorySize, GEMM_SMEM);

    cudaMemsetAsync(d_out, 0, (size_t)out_size * sizeof(float), 0);

    zero_counts_kernel<<<1, 32>>>();
    gating_kernel<<<(NTOK * 32 + 255) / 256, 256>>>(x, Wg, task);
    scan_kernel<<<1, 32>>>();

    // ffn1: h = gelu(x @ W1 + b1) -> fp16 hi/lo
    moe_gemm_kernel<DIM, true><<<dim3(NTOK / 128, HID / 128, NEXP), NTHR, GEMM_SMEM>>>(x, W1, b1, y, HID);
    // ffn2: y += gate * (h @ W2 + b2)
    moe_gemm_kernel<HID, false><<<dim3(NTOK / 128, DIM / 128, NEXP), NTHR, GEMM_SMEM>>>(x, W2, b2, y, DIM);
}

// round 13
// speedup vs baseline: 4.1695x; 1.3786x over previous
#include <cuda_runtime.h>
#include <cuda_fp16.h>
#include <math.h>
#include <stdint.h>

#define NTOK 4096
#define DIM  1024
#define HID  2048
#define NEXP 8
#define KSEL 2
#define NPAIR (NTOK * KSEL)

// ============ static scratch: ~32 MB ============
__device__ int   g_counts[NEXP];
__device__ int   g_offsets[NEXP + 1];
__device__ int   g_tokens[NEXP * NTOK];
__device__ float g_slotgate[NEXP * NTOK];
__device__ unsigned short g_h[(size_t)NPAIR * HID];   // fp16 h

// ============ PTX helpers (sm_80-level PTX; target is plain sm_100) ============
__device__ __forceinline__ uint32_t smem_u32(const void* p) {
    uint32_t a;
    asm("{ .reg .u64 t; cvta.to.shared.u64 t, %1; cvt.u32.u64 %0, t; }" : "=r"(a) : "l"(p));
    return a;
}
__device__ __forceinline__ void cp16(uint32_t dst, const void* src) {
    asm volatile("cp.async.cg.shared.global [%0], [%1], 16;" :: "r"(dst), "l"(src));
}
__device__ __forceinline__ void cp_commit() {
    asm volatile("cp.async.commit_group;" ::: "memory");
}
__device__ __forceinline__ void cp_wait_all() {
    asm volatile("cp.async.wait_group 0;" ::: "memory");
}
__device__ __forceinline__ void ldsm4(uint32_t* r, uint32_t addr) {
    asm volatile("ldmatrix.sync.aligned.m8n8.x4.shared.b16 {%0,%1,%2,%3}, [%4];"
                 : "=r"(r[0]), "=r"(r[1]), "=r"(r[2]), "=r"(r[3]) : "r"(addr));
}
__device__ __forceinline__ void ldsm4t(uint32_t* r, uint32_t addr) {
    asm volatile("ldmatrix.sync.aligned.m8n8.x4.trans.shared.b16 {%0,%1,%2,%3}, [%4];"
                 : "=r"(r[0]), "=r"(r[1]), "=r"(r[2]), "=r"(r[3]) : "r"(addr));
}
__device__ __forceinline__ void mma16816h(float* d, const uint32_t* a, const uint32_t* b) {
    asm volatile(
        "mma.sync.aligned.m16n8k16.row.col.f32.f16.f16.f32 "
        "{%0,%1,%2,%3}, {%4,%5,%6,%7}, {%8,%9}, {%0,%1,%2,%3};"
        : "+f"(d[0]), "+f"(d[1]), "+f"(d[2]), "+f"(d[3])
        : "r"(a[0]), "r"(a[1]), "r"(a[2]), "r"(a[3]), "r"(b[0]), "r"(b[1]));
}
// plain fp16 convert of float4 -> 4 packed halves
__device__ __forceinline__ uint2 cvt4h(float4 v) {
    __half2 a = __floats2half2_rn(v.x, v.y);
    __half2 b = __floats2half2_rn(v.z, v.w);
    return make_uint2(*reinterpret_cast<uint32_t*>(&a), *reinterpret_cast<uint32_t*>(&b));
}

// ============ routing ============
__global__ void zero_counts_kernel() {
    if (threadIdx.x < NEXP) g_counts[threadIdx.x] = 0;
}

__global__ void gating_kernel(const float* __restrict__ x,
                              const float* __restrict__ Wg,
                              const int* __restrict__ task_ptr) {
    int gw   = (blockIdx.x * blockDim.x + threadIdx.x) >> 5;
    int lane = threadIdx.x & 31;
    if (gw >= NTOK) return;

    const int task = task_ptr[0];
    const float* xr = x + (size_t)gw * DIM;
    const float* wg = Wg + (size_t)task * (DIM * NEXP);

    float s0 = 0.f, s1 = 0.f, s2 = 0.f, s3 = 0.f, s4 = 0.f, s5 = 0.f, s6 = 0.f, s7 = 0.f;
    for (int d = lane; d < DIM; d += 32) {
        float xv = xr[d];
        const float4* w4 = reinterpret_cast<const float4*>(wg + (size_t)d * NEXP);
        float4 a = w4[0];
        float4 b = w4[1];
        s0 += xv * a.x; s1 += xv * a.y; s2 += xv * a.z; s3 += xv * a.w;
        s4 += xv * b.x; s5 += xv * b.y; s6 += xv * b.z; s7 += xv * b.w;
    }
    #pragma unroll
    for (int off = 16; off > 0; off >>= 1) {
        s0 += __shfl_down_sync(0xffffffffu, s0, off);
        s1 += __shfl_down_sync(0xffffffffu, s1, off);
        s2 += __shfl_down_sync(0xffffffffu, s2, off);
        s3 += __shfl_down_sync(0xffffffffu, s3, off);
        s4 += __shfl_down_sync(0xffffffffu, s4, off);
        s5 += __shfl_down_sync(0xffffffffu, s5, off);
        s6 += __shfl_down_sync(0xffffffffu, s6, off);
        s7 += __shfl_down_sync(0xffffffffu, s7, off);
    }
    if (lane == 0) {
        float l[NEXP] = {s0, s1, s2, s3, s4, s5, s6, s7};
        float mx = l[0];
        #pragma unroll
        for (int e = 1; e < NEXP; e++) mx = fmaxf(mx, l[e]);
        float p[NEXP];
        float sum = 0.f;
        #pragma unroll
        for (int e = 0; e < NEXP; e++) { p[e] = expf(l[e] - mx); sum += p[e]; }
        float inv = 1.0f / sum;

        int i1 = 0;
        #pragma unroll
        for (int e = 1; e < NEXP; e++) if (l[e] > l[i1]) i1 = e;
        int i2 = (i1 == 0) ? 1 : 0;
        #pragma unroll
        for (int e = 0; e < NEXP; e++) if (e != i1 && l[e] > l[i2]) i2 = e;

        int pos1 = atomicAdd(&g_counts[i1], 1);
        g_tokens  [i1 * NTOK + pos1] = gw;
        g_slotgate[i1 * NTOK + pos1] = p[i1] * inv;
        int pos2 = atomicAdd(&g_counts[i2], 1);
        g_tokens  [i2 * NTOK + pos2] = gw;
        g_slotgate[i2 * NTOK + pos2] = p[i2] * inv;
    }
}

__global__ void scan_kernel() {
    if (threadIdx.x == 0) {
        int o = 0;
        #pragma unroll
        for (int e = 0; e < NEXP; e++) { g_offsets[e] = o; o += g_counts[e]; }
        g_offsets[NEXP] = o;
    }
}

// ============ mma.sync grouped GEMM (plain fp16, single pass, 512 threads) ============
// 128x128 tile, BK=32, 512 threads = 16 warps (4 m x 4 n); warp tile 32x32.
// SMEM: A [128][32] fp16 80B pitch, B [32][128] fp16 272B pitch. Double buffered.
#define BK     32
#define NTHR   512
#define ROWA   80
#define ROWB   272
#define A_TILE (128 * ROWA)                 // 10240
#define B_TILE (BK * ROWB)                  // 8704
#define STAGE_BYTES (A_TILE + B_TILE)       // 18944
// 2 stages = 37888 B -> static shared (< 48K), no attribute call needed

template<int KLEN, bool GELU>
__global__ __launch_bounds__(NTHR, 1)
void moe_gemm_kernel(const float* __restrict__ x,
                     const float* __restrict__ W,
                     const float* __restrict__ bias,
                     float* __restrict__ y,
                     int NTOT) {
    const int e      = blockIdx.z;
    const int count  = g_counts[e];
    const int mStart = blockIdx.x * 128;
    if (mStart >= count) return;
    const int nStart = blockIdx.y * 128;
    const int hBase  = g_offsets[e];

    __shared__ char smem[2 * STAGE_BYTES];

    const int tid  = threadIdx.x;
    const int wid  = tid >> 5;
    const int lane = tid & 31;
    const int wm   = wid & 3;        // 4 warps along M (32 rows)
    const int wn   = wid >> 2;       // 4 warps along N (32 cols)

    const float* Wb = W + (size_t)e * KLEN * NTOT;
    const int* toks = g_tokens + e * NTOK;

    float4 areg[2];
    float4 breg[2];

    // ffn2: A tile (fp16 h) straight gmem->smem via cp.async (512 chunks / 512 thr)
    auto issue_cpA = [&](int k0, char* stg) {
        int r  = tid >> 2;
        int c  = tid & 3;
        int gm = mStart + r;
        if (gm >= count) gm = count - 1;
        const unsigned short* src = g_h + (size_t)(hBase + gm) * HID + k0 + c * 8;
        cp16(smem_u32(stg + r * ROWA + c * 16), src);
        cp_commit();
    };

    auto load_regs = [&](int k0) {
        if (GELU) {
            #pragma unroll
            for (int j = 0; j < 2; j++) {
                int id = tid + NTHR * j;
                int r  = id >> 3;
                int c4 = id & 7;
                int gm = mStart + r;
                if (gm >= count) gm = count - 1;
                int tok = toks[gm];
                areg[j] = *reinterpret_cast<const float4*>(x + (size_t)tok * DIM + k0 + c4 * 4);
            }
        }
        #pragma unroll
        for (int j = 0; j < 2; j++) {
            int id = tid + NTHR * j;
            int kr = id >> 5;
            int c4 = id & 31;
            breg[j] = *reinterpret_cast<const float4*>(Wb + (size_t)(k0 + kr) * NTOT + nStart + c4 * 4);
        }
    };

    auto store_stage = [&](char* stg) {
        if (GELU) {
            #pragma unroll
            for (int j = 0; j < 2; j++) {
                int id = tid + NTHR * j;
                int r  = id >> 3;
                int c4 = id & 7;
                *reinterpret_cast<uint2*>(stg + r * ROWA + c4 * 8) = cvt4h(areg[j]);
            }
        }
        #pragma unroll
        for (int j = 0; j < 2; j++) {
            int id = tid + NTHR * j;
            int kr = id >> 5;
            int c4 = id & 31;
            *reinterpret_cast<uint2*>(stg + A_TILE + kr * ROWB + c4 * 8) = cvt4h(breg[j]);
        }
    };

    // warp tile 32x32: acc[mt][p*2+t][4]
    float acc[2][4][4];
    #pragma unroll
    for (int i = 0; i < 2; i++)
        #pragma unroll
        for (int j = 0; j < 4; j++)
            #pragma unroll
            for (int q = 0; q < 4; q++) acc[i][j][q] = 0.f;

    constexpr int NC = KLEN / BK;

    if (!GELU) issue_cpA(0, smem);
    load_regs(0);
    store_stage(smem);
    if (!GELU) cp_wait_all();
    __syncthreads();

    for (int k = 0; k < NC; k++) {
        char* cur = smem + (k & 1) * STAGE_BYTES;
        char* nxt = smem + ((k + 1) & 1) * STAGE_BYTES;
        const uint32_t sA = smem_u32(cur);
        const uint32_t sB = sA + A_TILE;

        if (k + 1 < NC) {
            if (!GELU) issue_cpA((k + 1) * BK, nxt);
            load_regs((k + 1) * BK);
        }

        #pragma unroll
        for (int kk = 0; kk < 2; kk++) {
            const int kof = kk * 16;

            uint32_t aa[2][4];
            #pragma unroll
            for (int mt = 0; mt < 2; mt++) {
                uint32_t off = (uint32_t)((wm * 32 + mt * 16 + (lane & 15)) * ROWA
                                          + (kof + ((lane & 16) ? 8 : 0)) * 2);
                ldsm4(aa[mt], sA + off);
            }
            uint32_t bb[2][4];
            #pragma unroll
            for (int p = 0; p < 2; p++) {
                int krow = kof + ((lane & 8) ? 8 : 0) + (lane & 7);
                int ncol = wn * 32 + p * 16 + ((lane & 16) ? 8 : 0);
                ldsm4t(bb[p], sB + (uint32_t)(krow * ROWB + ncol * 2));
            }

            #pragma unroll
            for (int mt = 0; mt < 2; mt++)
                #pragma unroll
                for (int p = 0; p < 2; p++)
                    #pragma unroll
                    for (int t = 0; t < 2; t++)
                        mma16816h(acc[mt][2 * p + t], aa[mt], &bb[p][2 * t]);
        }

        if (k + 1 < NC) {
            store_stage(nxt);
            if (!GELU) cp_wait_all();
        }
        __syncthreads();
    }

    // ---- epilogue: warp 32x32 block ----
    const int r0 = lane >> 2;
    const int c0 = 2 * (lane & 3);
    const float* gates = g_slotgate + e * NTOK;
    #pragma unroll
    for (int mt = 0; mt < 2; mt++) {
        #pragma unroll
        for (int nt = 0; nt < 4; nt++) {
            const float* d = acc[mt][nt];
            int lrow = mStart + wm * 32 + mt * 16 + r0;
            int col  = nStart + wn * 32 + nt * 8 + c0;
            float bs0 = bias[(size_t)e * NTOT + col];
            float bs1 = bias[(size_t)e * NTOT + col + 1];
            #pragma unroll
            for (int h = 0; h < 2; h++) {
                int rr = lrow + h * 8;
                if (rr >= count) continue;
                float v0 = d[2 * h + 0] + bs0;
                float v1 = d[2 * h + 1] + bs1;
                if (GELU) {
                    v0 = 0.5f * v0 * (1.0f + erff(v0 * 0.70710678118654752f));
                    v1 = 0.5f * v1 * (1.0f + erff(v1 * 0.70710678118654752f));
                    __half2 hv = __floats2half2_rn(v0, v1);
                    size_t ob = (size_t)(hBase + rr) * HID + col;
                    *reinterpret_cast<uint32_t*>(g_h + ob) = *reinterpret_cast<uint32_t*>(&hv);
                } else {
                    int   tok  = toks[rr];
                    float gate = gates[rr];
                    float* yr = y + (size_t)tok * DIM + col;
                    atomicAdd(&yr[0], gate * v0);
                    atomicAdd(&yr[1], gate * v1);
                }
            }
        }
    }
}

// ============ launch ============
extern "C" void kernel_launch(void* const* d_in, const int* in_sizes, int n_in,
                              void* d_out, int out_size) {
    const float* x    = (const float*)d_in[0];
    const float* Wg   = (const float*)d_in[1];
    const float* W1   = (const float*)d_in[2];
    const float* b1   = (const float*)d_in[3];
    const float* W2   = (const float*)d_in[4];
    const float* b2   = (const float*)d_in[5];
    const int*   task = (const int*)  d_in[6];
    float* y = (float*)d_out;

    cudaMemsetAsync(d_out, 0, (size_t)out_size * sizeof(float), 0);

    zero_counts_kernel<<<1, 32>>>();
    gating_kernel<<<(NTOK * 32 + 255) / 256, 256>>>(x, Wg, task);
    scan_kernel<<<1, 32>>>();

    // ffn1: h = gelu(x @ W1 + b1) -> fp16
    moe_gemm_kernel<DIM, true><<<dim3(NTOK / 128, HID / 128, NEXP), NTHR>>>(x, W1, b1, y, HID);
    // ffn2: y += gate * (h @ W2 + b2)
    moe_gemm_kernel<HID, false><<<dim3(NTOK / 128, DIM / 128, NEXP), NTHR>>>(x, W2, b2, y, DIM);
}